// round 17
// baseline (speedup 1.0000x reference)
#include <cuda_runtime.h>
#include <math.h>

#define H 1024
#define V 50257
#define L 512
#define NB16 ((V + 15) / 16)     // 3142 blocks of 16 rows in k_logits
#define NLC 32                   // l-chunks in attn partial stage

// ---------------- scratch (device globals; no allocations allowed) ----------
__device__ float g_s[L];              // raw attention scores
__device__ float g_part[NLC * H];     // partial attn_applied sums
__device__ float g_comb[2 * H];       // [embedded | attn_applied]
__device__ float g_x[H];              // relu(combined @ Wc^T + bc)
__device__ float g_gates[6 * H];      // gi(3H) | gh(3H)
__device__ float g_h[H];              // h_new
__device__ float g_logits[V];
__device__ float g_pm[NB16];          // per-block max
__device__ float g_ps[NB16];          // per-block sum exp
__device__ int   g_cnt[2];            // last-block tickets (reset by releaser)

__inline__ __device__ float warpSum(float v) {
    #pragma unroll
    for (int o = 16; o; o >>= 1) v += __shfl_xor_sync(0xffffffffu, v, o);
    return v;
}
__inline__ __device__ float warpMax(float v) {
    #pragma unroll
    for (int o = 16; o; o >>= 1) v = fmaxf(v, __shfl_xor_sync(0xffffffffu, v, o));
    return v;
}

// ---------------------------------------------------------------------------
// K_A: blocks 0..63 -> scores s[l]=h0.enc[l];  blocks 64..255 -> gh = whh.h0
// Both depend only on kernel inputs (whh half of GRU off the critical path).
// ---------------------------------------------------------------------------
__global__ void __launch_bounds__(256) k_a(const float* __restrict__ hid,
                                           const float* __restrict__ enc,
                                           const float* __restrict__ whh) {
    __shared__ float4 vs[H / 4];
    int t = threadIdx.x;
    vs[t] = ((const float4*)hid)[t];
    __syncthreads();
    int warp = t >> 5, lane = t & 31;
    if (blockIdx.x < 64) {
        int l = blockIdx.x * 8 + warp;
        const float4* e4 = (const float4*)(enc + (size_t)l * H);
        float a0 = 0.f, a1 = 0.f;
        #pragma unroll
        for (int k = 0; k < 4; k++) {
            float4 ea = e4[lane + 32 * k],       ba = vs[lane + 32 * k];
            float4 eb = e4[lane + 32 * (k + 4)], bb = vs[lane + 32 * (k + 4)];
            a0 += ea.x * ba.x + ea.y * ba.y + ea.z * ba.z + ea.w * ba.w;
            a1 += eb.x * bb.x + eb.y * bb.y + eb.z * bb.z + eb.w * bb.w;
        }
        float acc = warpSum(a0 + a1);
        if (lane == 0) g_s[l] = acc;
    } else {
        int r0 = (blockIdx.x - 64) * 16 + warp * 2;     // 0..3070 (whh rows)
        const float4* w0 = (const float4*)(whh + (size_t)r0 * H);
        const float4* w1 = (const float4*)(whh + (size_t)(r0 + 1) * H);
        float acc0 = 0.f, acc1 = 0.f;
        #pragma unroll
        for (int k = 0; k < 8; k++) {
            float4 b  = vs[lane + 32 * k];
            float4 a0 = __ldcs(w0 + lane + 32 * k);
            float4 a1 = __ldcs(w1 + lane + 32 * k);
            acc0 += a0.x * b.x + a0.y * b.y + a0.z * b.z + a0.w * b.w;
            acc1 += a1.x * b.x + a1.y * b.y + a1.z * b.z + a1.w * b.w;
        }
        acc0 = warpSum(acc0);
        acc1 = warpSum(acc1);
        if (lane == 0) {
            g_gates[3 * H + r0]     = acc0;
            g_gates[3 * H + r0 + 1] = acc1;
        }
    }
}

// ---------------------------------------------------------------------------
// K_B: softmax (redundant per block) + attn partials; LAST BLOCK reduces the
// partials into comb[H..2H) and gathers the embedding into comb[0..H).
// grid 128 = 4 h-chunks x 32 l-chunks.
// ---------------------------------------------------------------------------
__global__ void __launch_bounds__(256) k_b(const float* __restrict__ enc,
                                           const float* __restrict__ emb,
                                           const long long* __restrict__ tok,
                                           float* __restrict__ out_attn) {
    __shared__ float ws[L];
    __shared__ float red[8];
    __shared__ float bcast;
    __shared__ int lastflag;
    int t = threadIdx.x;
    int hc = blockIdx.x & 3;
    int lc = blockIdx.x >> 2;

    float s0 = g_s[t], s1 = g_s[t + 256];
    float m = warpMax(fmaxf(s0, s1));
    if ((t & 31) == 0) red[t >> 5] = m;
    __syncthreads();
    if (t == 0) {
        float mm = red[0];
        #pragma unroll
        for (int i = 1; i < 8; i++) mm = fmaxf(mm, red[i]);
        bcast = mm;
    }
    __syncthreads();
    float M = bcast;
    float e0 = expf(s0 - M), e1 = expf(s1 - M);
    __syncthreads();
    float s = warpSum(e0 + e1);
    if ((t & 31) == 0) red[t >> 5] = s;
    __syncthreads();
    if (t == 0) {
        float ss = 0.f;
        #pragma unroll
        for (int i = 0; i < 8; i++) ss += red[i];
        bcast = 1.f / ss;
    }
    __syncthreads();
    float inv = bcast;
    ws[t] = e0 * inv;
    ws[t + 256] = e1 * inv;
    __syncthreads();

    if (hc == 0 && t < 16) out_attn[lc * 16 + t] = ws[lc * 16 + t];

    int h = hc * 256 + t;
    const float* ep = enc + (size_t)(lc * 16) * H + h;
    float acc = 0.f;
    #pragma unroll
    for (int l = 0; l < 16; l++) acc += ws[lc * 16 + l] * ep[(size_t)l * H];
    g_part[lc * H + h] = acc;

    // ---- last-block epilogue: attnr ----
    __threadfence();
    __syncthreads();
    if (t == 0) {
        int ticket = atomicAdd(&g_cnt[0], 1);
        lastflag = (ticket == 127);
        if (lastflag) atomicExch(&g_cnt[0], 0);   // replay-safe reset
    }
    __syncthreads();
    if (lastflag) {
        __threadfence();
        long long tk = tok[0];
        #pragma unroll
        for (int j = 0; j < 4; j++) {
            int hh = j * 256 + t;
            float a = 0.f;
            #pragma unroll
            for (int i = 0; i < NLC; i++) a += g_part[i * H + hh];
            g_comb[H + hh] = a;
            g_comb[hh] = emb[(size_t)tk * H + hh];
        }
    }
}

// ---------------------------------------------------------------------------
// K_C: x[row] = relu(Wc[row].comb + bc); 1 row/warp, 16 batched loads.
// ---------------------------------------------------------------------------
__global__ void __launch_bounds__(256) k_c(const float* __restrict__ wc,
                                           const float* __restrict__ bc) {
    __shared__ float4 cs[2 * H / 4];
    int t = threadIdx.x;
    cs[t] = ((const float4*)g_comb)[t];
    cs[t + 256] = ((const float4*)g_comb)[t + 256];
    __syncthreads();
    int warp = t >> 5, lane = t & 31;
    int row = blockIdx.x * 8 + warp;
    const float4* w4 = (const float4*)(wc + (size_t)row * 2 * H);
    float a0 = 0.f, a1 = 0.f;
    #pragma unroll
    for (int k = 0; k < 8; k++) {
        float4 wa = __ldcs(w4 + lane + 32 * k);
        float4 ca = cs[lane + 32 * k];
        float4 wb = __ldcs(w4 + 256 + lane + 32 * k);
        float4 cb = cs[256 + lane + 32 * k];
        a0 += wa.x * ca.x + wa.y * ca.y + wa.z * ca.z + wa.w * ca.w;
        a1 += wb.x * cb.x + wb.y * cb.y + wb.z * cb.z + wb.w * cb.w;
    }
    float acc = warpSum(a0 + a1);
    if (lane == 0) g_x[row] = fmaxf(acc + bc[row], 0.f);
}

// ---------------------------------------------------------------------------
// K_D: gi = wih.x (3072 rows, 2 rows/warp, 192 blocks); LAST BLOCK computes
// the GRU gates -> g_h, out_h.
// ---------------------------------------------------------------------------
__global__ void __launch_bounds__(256) k_d(const float* __restrict__ wih,
                                           const float* __restrict__ bih,
                                           const float* __restrict__ bhh,
                                           const float* __restrict__ hid,
                                           float* __restrict__ out_h) {
    __shared__ float4 xs[H / 4];
    __shared__ int lastflag;
    int t = threadIdx.x;
    xs[t] = ((const float4*)g_x)[t];
    __syncthreads();
    int warp = t >> 5, lane = t & 31;
    int r0 = blockIdx.x * 16 + warp * 2;
    const float4* w0 = (const float4*)(wih + (size_t)r0 * H);
    const float4* w1 = (const float4*)(wih + (size_t)(r0 + 1) * H);
    float acc0 = 0.f, acc1 = 0.f;
    #pragma unroll
    for (int k = 0; k < 8; k++) {
        float4 b  = xs[lane + 32 * k];
        float4 a0 = __ldcs(w0 + lane + 32 * k);
        float4 a1 = __ldcs(w1 + lane + 32 * k);
        acc0 += a0.x * b.x + a0.y * b.y + a0.z * b.z + a0.w * b.w;
        acc1 += a1.x * b.x + a1.y * b.y + a1.z * b.z + a1.w * b.w;
    }
    acc0 = warpSum(acc0);
    acc1 = warpSum(acc1);
    if (lane == 0) {
        g_gates[r0]     = acc0;
        g_gates[r0 + 1] = acc1;
    }

    // ---- last-block epilogue: gates ----
    __threadfence();
    __syncthreads();
    if (t == 0) {
        int ticket = atomicAdd(&g_cnt[1], 1);
        lastflag = (ticket == 191);
        if (lastflag) atomicExch(&g_cnt[1], 0);
    }
    __syncthreads();
    if (lastflag) {
        __threadfence();
        #pragma unroll
        for (int j = 0; j < 4; j++) {
            int h = j * 256 + t;
            float gi_r = g_gates[h],         gh_r = g_gates[3 * H + h];
            float gi_z = g_gates[H + h],     gh_z = g_gates[4 * H + h];
            float gi_n = g_gates[2 * H + h], gh_n = g_gates[5 * H + h];
            float r = 1.f / (1.f + expf(-(gi_r + bih[h]         + gh_r + bhh[h])));
            float z = 1.f / (1.f + expf(-(gi_z + bih[H + h]     + gh_z + bhh[H + h])));
            float n = tanhf(gi_n + bih[2 * H + h] + r * (gh_n + bhh[2 * H + h]));
            float hn = (1.f - z) * n + z * hid[h];
            g_h[h] = hn;
            out_h[h] = hn;
        }
    }
}

// ---------------------------------------------------------------------------
// K_LOGITS: logits + per-block partial logsumexp; 2 rows/warp, 16 rows/block.
// ---------------------------------------------------------------------------
__global__ void __launch_bounds__(256) k_logits(const float* __restrict__ ow,
                                                const float* __restrict__ ob) {
    __shared__ float4 hs[H / 4];
    __shared__ float lg[16];
    int t = threadIdx.x;
    hs[t] = ((const float4*)g_h)[t];
    __syncthreads();
    int warp = t >> 5, lane = t & 31;
    int v0 = blockIdx.x * 16 + warp * 2;
    float l0 = -INFINITY, l1 = -INFINITY;
    bool r0 = v0 < V, r1 = (v0 + 1) < V;
    const float4* w0 = (const float4*)(ow + (size_t)v0 * H);
    const float4* w1 = (const float4*)(ow + (size_t)(v0 + 1) * H);
    float acc0 = 0.f, acc1 = 0.f;
    if (r1) {
        #pragma unroll
        for (int k = 0; k < 8; k++) {
            float4 bq = hs[lane + 32 * k];
            float4 a0 = __ldcs(w0 + lane + 32 * k);
            float4 a1 = __ldcs(w1 + lane + 32 * k);
            acc0 += a0.x * bq.x + a0.y * bq.y + a0.z * bq.z + a0.w * bq.w;
            acc1 += a1.x * bq.x + a1.y * bq.y + a1.z * bq.z + a1.w * bq.w;
        }
    } else if (r0) {
        #pragma unroll
        for (int k = 0; k < 8; k++) {
            float4 bq = hs[lane + 32 * k];
            float4 a0 = __ldcs(w0 + lane + 32 * k);
            acc0 += a0.x * bq.x + a0.y * bq.y + a0.z * bq.z + a0.w * bq.w;
        }
    }
    acc0 = warpSum(acc0);
    acc1 = warpSum(acc1);
    if (lane == 0) {
        if (r0) { l0 = acc0 + ob[v0];     g_logits[v0] = l0; }
        if (r1) { l1 = acc1 + ob[v0 + 1]; g_logits[v0 + 1] = l1; }
        lg[warp * 2]     = l0;
        lg[warp * 2 + 1] = l1;
    }
    __syncthreads();
    if (t == 0) {
        float m = -INFINITY;
        #pragma unroll
        for (int i = 0; i < 16; i++) m = fmaxf(m, lg[i]);
        float s = 0.f;
        #pragma unroll
        for (int i = 0; i < 16; i++) s += (lg[i] == -INFINITY) ? 0.f : expf(lg[i] - m);
        g_pm[blockIdx.x] = m;
        g_ps[blockIdx.x] = s;
    }
}

// K_LOGP: per-block redundant LSE combine (from L2) + logp write. 99 x 512
__global__ void k_logp(float* __restrict__ out) {
    __shared__ float sm[16], ss[16];
    __shared__ float bM, bLS;
    int t = threadIdx.x;
    float m = -INFINITY, s = 0.f;
    for (int i = t; i < NB16; i += 512) {
        float bm = g_pm[i], bs = g_ps[i];
        float nm = fmaxf(m, bm);
        s = s * expf(m - nm) + bs * expf(bm - nm);
        m = nm;
    }
    #pragma unroll
    for (int o = 16; o; o >>= 1) {
        float om = __shfl_xor_sync(0xffffffffu, m, o);
        float os = __shfl_xor_sync(0xffffffffu, s, o);
        float nm = fmaxf(m, om);
        s = s * expf(m - nm) + os * expf(om - nm);
        m = nm;
    }
    if ((t & 31) == 0) { sm[t >> 5] = m; ss[t >> 5] = s; }
    __syncthreads();
    if (t == 0) {
        float M = sm[0], S = ss[0];
        #pragma unroll
        for (int i = 1; i < 16; i++) {
            float nm = fmaxf(M, sm[i]);
            S = S * expf(M - nm) + ss[i] * expf(sm[i] - nm);
            M = nm;
        }
        bM = M;
        bLS = logf(S);
    }
    __syncthreads();
    float M = bM, LS = bLS;
    for (int v = blockIdx.x * 512 + t; v < V; v += gridDim.x * 512)
        out[v] = g_logits[v] - M - LS;
}

extern "C" void kernel_launch(void* const* d_in, const int* in_sizes, int n_in,
                              void* d_out, int out_size) {
    const long long* tok = (const long long*)d_in[0];
    const float* hid  = (const float*)d_in[1];
    const float* enc  = (const float*)d_in[2];
    const float* emb  = (const float*)d_in[3];
    const float* wc   = (const float*)d_in[4];
    const float* bc   = (const float*)d_in[5];
    const float* wih  = (const float*)d_in[6];
    const float* whh  = (const float*)d_in[7];
    const float* bih  = (const float*)d_in[8];
    const float* bhh  = (const float*)d_in[9];
    const float* ow   = (const float*)d_in[10];
    const float* ob   = (const float*)d_in[11];

    float* out = (float*)d_out;
    float* out_logp = out;
    float* out_h    = out + V;
    float* out_attn = out + V + H;

    k_a<<<256, 256>>>(hid, enc, whh);                  // scores ∥ whh·h0
    k_b<<<128, 256>>>(enc, emb, tok, out_attn);        // softmax+partials (+attnr)
    k_c<<<128, 256>>>(wc, bc);                         // combine -> x
    k_d<<<192, 256>>>(wih, bih, bhh, hid, out_h);      // wih·x (+gates)
    k_logits<<<NB16, 256>>>(ow, ob);
    k_logp<<<99, 512>>>(out_logp);
}